// round 6
// baseline (speedup 1.0000x reference)
#include <cuda_runtime.h>

// Problem constants
#define DIMC 192
#define RR   48            // DIM/RED
#define BB   4
#define HH   256
#define WW   256
#define PLANE (HH*WW)      // 65536
#define NPLANES (BB*DIMC)  // 768
#define EPS_BN 1e-5f

// Scratch (no allocations allowed)
__device__ float g_partial[NPLANES * 4];   // per-quarter-plane sums
__device__ float g_wt[NPLANES * 4];        // 4 surviving masked taps per plane

// ---------------------------------------------------------------------------
// Kernel 1: partial sums for channel-wise mean. 3072 blocks x 256 threads.
// Each block reduces one quarter (16384 floats) of one plane.
// 4 independent accumulators -> deeper load pipelining.
// ---------------------------------------------------------------------------
__global__ void __launch_bounds__(256)
pool_partial_kernel(const float* __restrict__ x) {
    int bid = blockIdx.x;                  // [0, 3072)
    int plane = bid >> 2;
    int quarter = bid & 3;
    const float4* p = reinterpret_cast<const float4*>(
        x + (size_t)plane * PLANE + quarter * (PLANE / 4));
    float s0 = 0.f, s1 = 0.f, s2 = 0.f, s3 = 0.f;
    #pragma unroll
    for (int j = 0; j < 4; ++j) {
        float4 v0 = p[threadIdx.x + (4*j+0) * 256];
        float4 v1 = p[threadIdx.x + (4*j+1) * 256];
        float4 v2 = p[threadIdx.x + (4*j+2) * 256];
        float4 v3 = p[threadIdx.x + (4*j+3) * 256];
        s0 += (v0.x + v0.y) + (v0.z + v0.w);
        s1 += (v1.x + v1.y) + (v1.z + v1.w);
        s2 += (v2.x + v2.y) + (v2.z + v2.w);
        s3 += (v3.x + v3.y) + (v3.z + v3.w);
    }
    float s = (s0 + s1) + (s2 + s3);
    #pragma unroll
    for (int o = 16; o > 0; o >>= 1) s += __shfl_down_sync(0xffffffffu, s, o);
    __shared__ float sm[8];
    int lane = threadIdx.x & 31, w = threadIdx.x >> 5;
    if (lane == 0) sm[w] = s;
    __syncthreads();
    if (threadIdx.x < 8) {
        float v = sm[threadIdx.x];
        #pragma unroll
        for (int o = 4; o > 0; o >>= 1) v += __shfl_down_sync(0xffu, v, o);
        if (threadIdx.x == 0) g_partial[bid] = v;
    }
}

// ---------------------------------------------------------------------------
// Kernel 2 (fused): per-block redundant t = relu(BN(pooled @ w1^T)), then
// warp-per-weight dot products for the 4 surviving masked taps.
// grid = 192 blocks x 256 threads; each block produces 16 weights
// (8 warps x 2 weights). w1/g_partial reads broadcast via L2.
// ---------------------------------------------------------------------------
__global__ void __launch_bounds__(256)
fused_wt_kernel(const float* __restrict__ w1,
                const float* __restrict__ gamma,
                const float* __restrict__ beta,
                const float* __restrict__ rmean,
                const float* __restrict__ rvar,
                const float* __restrict__ w2,
                const float* __restrict__ b2) {
    __shared__ float sp[NPLANES];     // pooled means
    __shared__ float st[BB * RR];     // hidden t
    for (int j = threadIdx.x; j < NPLANES; j += 256) {
        sp[j] = (g_partial[4*j] + g_partial[4*j+1] + g_partial[4*j+2] + g_partial[4*j+3])
                * (1.f / (float)PLANE);
    }
    __syncthreads();
    if (threadIdx.x < BB * RR) {
        int b = threadIdx.x / RR;
        int r = threadIdx.x % RR;
        const float* pb = &sp[b * DIMC];
        const float* wr = &w1[r * DIMC];
        float acc = 0.f;
        #pragma unroll 4
        for (int k = 0; k < DIMC; ++k) acc = fmaf(pb[k], wr[k], acc);
        acc = gamma[r] * (acc - rmean[r]) * rsqrtf(rvar[r] + EPS_BN) + beta[r];
        st[threadIdx.x] = fmaxf(acc, 0.f);
    }
    __syncthreads();

    int lane = threadIdx.x & 31;
    int warp = threadIdx.x >> 5;      // 0..7
    #pragma unroll
    for (int i = 0; i < 2; ++i) {
        int idx = blockIdx.x * 16 + warp * 2 + i;   // [0, 3072)
        int b   = idx / (DIMC * 4);
        int rem = idx % (DIMC * 4);
        int c   = rem >> 2;
        int k   = rem & 3;
        int row = c * 9 + k;                        // w2 row (K*K=9 taps)
        const float* wr = &w2[(size_t)row * RR];
        const float* tb = &st[b * RR];
        float acc = tb[lane] * wr[lane];
        if (lane < 16) acc = fmaf(tb[lane + 32], wr[lane + 32], acc);
        #pragma unroll
        for (int o = 16; o > 0; o >>= 1) acc += __shfl_down_sync(0xffffffffu, acc, o);
        if (lane == 0) g_wt[idx] = acc + b2[row];
    }
}

// ---------------------------------------------------------------------------
// Kernel 3: masked depthwise conv (4 taps) + bias.
// out[y][x] = w0*X[y-1][x-1] + w1*X[y-1][x] + w2*X[y-1][x+1] + w3*X[y][x-1] + b
// Block = 256 threads = 8 warps = 8 rows; each lane owns 8 consecutive cols
// (two float4s). All x-halos come from warp shuffles (lane 0 / lane 31 are the
// true image edges -> zero). Streaming stores keep x resident in L2.
// grid: 768 planes * 32 row-groups.
// ---------------------------------------------------------------------------
__global__ void __launch_bounds__(256, 8)
conv_kernel(const float* __restrict__ x,
            const float* __restrict__ bias,
            float* __restrict__ out) {
    int plane = blockIdx.x >> 5;
    int rg    = blockIdx.x & 31;
    int lane  = threadIdx.x & 31;
    int ty    = threadIdx.x >> 5;
    int y     = rg * 8 + ty;
    int x0    = lane << 3;

    const float* cur = x + (size_t)plane * PLANE + y * WW;

    float4 c0 = *reinterpret_cast<const float4*>(cur + x0);
    float4 c1 = *reinterpret_cast<const float4*>(cur + x0 + 4);
    float4 a0 = make_float4(0.f, 0.f, 0.f, 0.f);
    float4 a1 = a0;
    if (y > 0) {
        const float* ab = cur - WW;
        a0 = *reinterpret_cast<const float4*>(ab + x0);
        a1 = *reinterpret_cast<const float4*>(ab + x0 + 4);
    }

    // halos via shuffle (row edges are real image edges -> 0)
    float al = __shfl_up_sync(0xffffffffu, a1.w, 1);
    float cl = __shfl_up_sync(0xffffffffu, c1.w, 1);
    float ar = __shfl_down_sync(0xffffffffu, a0.x, 1);
    if (lane == 0)  { al = 0.f; cl = 0.f; }
    if (lane == 31) { ar = 0.f; }

    const float4 w = *reinterpret_cast<const float4*>(g_wt + plane * 4);
    float bv = __ldg(&bias[plane % DIMC]);

    float4 o0, o1;
    o0.x = fmaf(w.x, al,   fmaf(w.y, a0.x, fmaf(w.z, a0.y, fmaf(w.w, cl,   bv))));
    o0.y = fmaf(w.x, a0.x, fmaf(w.y, a0.y, fmaf(w.z, a0.z, fmaf(w.w, c0.x, bv))));
    o0.z = fmaf(w.x, a0.y, fmaf(w.y, a0.z, fmaf(w.z, a0.w, fmaf(w.w, c0.y, bv))));
    o0.w = fmaf(w.x, a0.z, fmaf(w.y, a0.w, fmaf(w.z, a1.x, fmaf(w.w, c0.z, bv))));
    o1.x = fmaf(w.x, a0.w, fmaf(w.y, a1.x, fmaf(w.z, a1.y, fmaf(w.w, c0.w, bv))));
    o1.y = fmaf(w.x, a1.x, fmaf(w.y, a1.y, fmaf(w.z, a1.z, fmaf(w.w, c1.x, bv))));
    o1.z = fmaf(w.x, a1.y, fmaf(w.y, a1.z, fmaf(w.z, a1.w, fmaf(w.w, c1.y, bv))));
    o1.w = fmaf(w.x, a1.z, fmaf(w.y, a1.w, fmaf(w.z, ar,   fmaf(w.w, c1.z, bv))));

    float* op = out + (size_t)plane * PLANE + y * WW + x0;
    __stcs(reinterpret_cast<float4*>(op), o0);
    __stcs(reinterpret_cast<float4*>(op) + 1, o1);
}

// ---------------------------------------------------------------------------
extern "C" void kernel_launch(void* const* d_in, const int* in_sizes, int n_in,
                              void* d_out, int out_size) {
    const float* x     = (const float*)d_in[0];
    const float* w1    = (const float*)d_in[1];
    const float* gamma = (const float*)d_in[2];
    const float* beta  = (const float*)d_in[3];
    const float* rmean = (const float*)d_in[4];
    const float* rvar  = (const float*)d_in[5];
    const float* w2    = (const float*)d_in[6];
    const float* b2    = (const float*)d_in[7];
    const float* bias  = (const float*)d_in[8];
    float* out = (float*)d_out;

    pool_partial_kernel<<<NPLANES * 4, 256>>>(x);
    fused_wt_kernel<<<192, 256>>>(w1, gamma, beta, rmean, rvar, w2, b2);
    conv_kernel<<<NPLANES * 32, 256>>>(x, bias, out);
}